// round 5
// baseline (speedup 1.0000x reference)
#include <cuda_runtime.h>
#include <math.h>

#define F_DIM   2048
#define N_DIM   10000
#define B_DIM   8
#define J_DIM   10
#define R_DIM   20
#define H1_DIM  200
#define H2_DIM  100
#define FCHUNKS 8
#define FCHUNK  256                 /* F_DIM / FCHUNKS */
#define NTILE   512                 /* n per CTA: 128 threads * 4 */
#define HVEC    (2 * R_DIM * J_DIM) /* 400 */

// Scratch (static device globals -- no allocation allowed)
__device__ float g_part[FCHUNKS * B_DIM * J_DIM * N_DIM]; // 25.6 MB partial sums
__device__ float g_h[B_DIM * HVEC];                       // [8][400] MLP input

__device__ __forceinline__ void fma2(unsigned long long &acc,
                                     unsigned long long a,
                                     unsigned long long b) {
    // packed 2x fp32 FMA (FFMA2) -- only reachable via PTX f32x2
    asm("fma.rn.f32x2 %0, %1, %2, %0;" : "+l"(acc) : "l"(a), "l"(b));
}

// ---------------------------------------------------------------------------
// Kernel 1: streaming skinny GEMM. Each thread: one b, 4 consecutive n,
// one F-chunk of 256. Accumulators: 10 j x 2 f32x2 pairs. Weights splatted
// {w,w} in smem, read via broadcast LDS.128 (2 j per load).
// ---------------------------------------------------------------------------
__global__ __launch_bounds__(128) void k_conv(const float* __restrict__ x,
                                              const float* __restrict__ conv_w) {
    __shared__ __align__(16) unsigned long long wsp[FCHUNK * J_DIM]; // 20 KB

    const int b     = blockIdx.y;
    const int fc    = blockIdx.z;
    const int fbase = fc * FCHUNK;

    // Cooperative weight load + splat: wsp[fl*10 + j] = {w[j][fbase+fl], same}
    for (int idx = threadIdx.x; idx < FCHUNK * J_DIM; idx += 128) {
        const int fl = idx / J_DIM, j = idx % J_DIM;
        const float w = conv_w[j * F_DIM + fbase + fl];
        float2 ww = make_float2(w, w);
        wsp[idx] = *reinterpret_cast<unsigned long long*>(&ww);
    }
    __syncthreads();

    const int n0 = blockIdx.x * NTILE + threadIdx.x * 4;
    if (n0 >= N_DIM) return;   // N_DIM % 4 == 0, so no partial vectors

    unsigned long long acc[2 * J_DIM];
#pragma unroll
    for (int i = 0; i < 2 * J_DIM; ++i) acc[i] = 0ull;

    const float* xp = x + (b * F_DIM + fbase) * N_DIM + n0;

#pragma unroll 4
    for (int fl = 0; fl < FCHUNK; ++fl) {
        const ulonglong2 xv = *reinterpret_cast<const ulonglong2*>(xp); // 4 n's
        xp += N_DIM;
        const ulonglong2* wp = reinterpret_cast<const ulonglong2*>(&wsp[fl * J_DIM]);
#pragma unroll
        for (int jj = 0; jj < 5; ++jj) {       // 2 j per iteration
            const ulonglong2 w2 = wp[jj];
            fma2(acc[4 * jj + 0], xv.x, w2.x);
            fma2(acc[4 * jj + 1], xv.y, w2.x);
            fma2(acc[4 * jj + 2], xv.x, w2.y);
            fma2(acc[4 * jj + 3], xv.y, w2.y);
        }
    }

    float* pout = g_part + (fc * B_DIM * J_DIM + b * J_DIM) * N_DIM + n0;
#pragma unroll
    for (int j = 0; j < J_DIM; ++j) {
        ulonglong2 v;
        v.x = acc[2 * j];
        v.y = acc[2 * j + 1];
        *reinterpret_cast<ulonglong2*>(pout + j * N_DIM) = v; // STG.128
    }
}

// ---------------------------------------------------------------------------
// Kernel 2: per (b,j) row -- sum F-chunk partials into smem, then:
//   Phase A: 20 max-extraction passes (remove with -INF, record idx+val)
//   restore removed values
//   Phase B: 20 min-extraction passes (remove with +INF)
// Two phases avoid sentinel cross-contamination (the prior NaN bug: a -INF
// max-removal sentinel was picked up by the min scan and vice versa).
// Bias added post-selection (uniform shift, selection-invariant).
// ---------------------------------------------------------------------------
__global__ __launch_bounds__(256) void k_minmax(const float* __restrict__ conv_b) {
    const int row = blockIdx.x;            // b*10 + j
    const int tid = threadIdx.x;
    __shared__ float vals[N_DIM];          // 40 KB
    __shared__ float rv[8];
    __shared__ int   ri[8];
    __shared__ int   rem_idx[R_DIM];
    __shared__ float rem_val[R_DIM];

    for (int n = tid; n < N_DIM; n += 256) {
        float s = 0.f;
#pragma unroll
        for (int fcc = 0; fcc < FCHUNKS; ++fcc)
            s += g_part[(fcc * B_DIM * J_DIM + row) * N_DIM + n];
        vals[n] = s;
    }
    __syncthreads();

    const int  lane = tid & 31, wid = tid >> 5;
    const int  j    = row % J_DIM;
    const float bias = conv_b[j];
    float* out = g_h + (row / J_DIM) * HVEC + j * (2 * R_DIM);

    // ---- Phase A: top-R descending ----
    for (int pass = 0; pass < R_DIM; ++pass) {
        float mx = -INFINITY;
        int   mxi = 0;
        for (int n = tid; n < N_DIM; n += 256) {
            const float v = vals[n];
            if (v > mx) { mx = v; mxi = n; }
        }
#pragma unroll
        for (int off = 16; off > 0; off >>= 1) {
            float o  = __shfl_down_sync(0xffffffffu, mx, off);
            int   oi = __shfl_down_sync(0xffffffffu, mxi, off);
            if (o > mx) { mx = o; mxi = oi; }
        }
        if (lane == 0) { rv[wid] = mx; ri[wid] = mxi; }
        __syncthreads();
        if (tid == 0) {
            for (int w = 1; w < 8; ++w)
                if (rv[w] > mx) { mx = rv[w]; mxi = ri[w]; }
            out[pass] = mx + bias;          // pass-th largest, descending
            rem_idx[pass] = mxi;
            rem_val[pass] = mx;
            vals[mxi] = -INFINITY;
        }
        __syncthreads();
    }

    // restore removed top values (exact)
    if (tid < R_DIM) vals[rem_idx[tid]] = rem_val[tid];
    __syncthreads();

    // ---- Phase B: bottom-R, k-th smallest -> position 2R-1-pass ----
    for (int pass = 0; pass < R_DIM; ++pass) {
        float mn = INFINITY;
        int   mni = 0;
        for (int n = tid; n < N_DIM; n += 256) {
            const float v = vals[n];
            if (v < mn) { mn = v; mni = n; }
        }
#pragma unroll
        for (int off = 16; off > 0; off >>= 1) {
            float o  = __shfl_down_sync(0xffffffffu, mn, off);
            int   oi = __shfl_down_sync(0xffffffffu, mni, off);
            if (o < mn) { mn = o; mni = oi; }
        }
        if (lane == 0) { rv[wid] = mn; ri[wid] = mni; }
        __syncthreads();
        if (tid == 0) {
            for (int w = 1; w < 8; ++w)
                if (rv[w] < mn) { mn = rv[w]; mni = ri[w]; }
            out[2 * R_DIM - 1 - pass] = mn + bias;  // smallest -> slot 39, etc.
            vals[mni] = INFINITY;
        }
        __syncthreads();
    }
}

// ---------------------------------------------------------------------------
// Kernel 3: tiny MLP, one CTA per batch row.
// ---------------------------------------------------------------------------
__device__ __forceinline__ float sigmoidf_(float z) {
    return 1.f / (1.f + expf(-z));
}

__global__ __launch_bounds__(256) void k_mlp(const float* __restrict__ w1,
                                             const float* __restrict__ b1,
                                             const float* __restrict__ w2,
                                             const float* __restrict__ b2,
                                             const float* __restrict__ w3,
                                             const float* __restrict__ b3,
                                             float* __restrict__ out) {
    const int b   = blockIdx.x;
    const int tid = threadIdx.x;
    __shared__ float s0[HVEC], s1[H1_DIM], s2[H2_DIM];

    for (int i = tid; i < HVEC; i += 256) s0[i] = g_h[b * HVEC + i];
    __syncthreads();

    if (tid < H1_DIM) {
        float a = b1[tid];
        for (int i = 0; i < HVEC; ++i) a += s0[i] * w1[i * H1_DIM + tid];
        s1[tid] = sigmoidf_(a);
    }
    __syncthreads();

    if (tid < H2_DIM) {
        float a = b2[tid];
        for (int i = 0; i < H1_DIM; ++i) a += s1[i] * w2[i * H2_DIM + tid];
        s2[tid] = sigmoidf_(a);
    }
    __syncthreads();

    if (tid < 2) {
        float a = b3[tid];
        for (int i = 0; i < H2_DIM; ++i) a += s2[i] * w3[i * 2 + tid];
        out[b * 2 + tid] = a;
    }
}

// ---------------------------------------------------------------------------
extern "C" void kernel_launch(void* const* d_in, const int* in_sizes, int n_in,
                              void* d_out, int out_size) {
    const float* x      = (const float*)d_in[0];
    const float* conv_w = (const float*)d_in[1];
    const float* conv_b = (const float*)d_in[2];
    const float* w1     = (const float*)d_in[3];
    const float* b1     = (const float*)d_in[4];
    const float* w2     = (const float*)d_in[5];
    const float* b2     = (const float*)d_in[6];
    const float* w3     = (const float*)d_in[7];
    const float* b3     = (const float*)d_in[8];
    float* out = (float*)d_out;

    dim3 g1((N_DIM + NTILE - 1) / NTILE, B_DIM, FCHUNKS); // 20 x 8 x 8
    k_conv<<<g1, 128>>>(x, conv_w);
    k_minmax<<<B_DIM * J_DIM, 256>>>(conv_b);
    k_mlp<<<B_DIM, 256>>>(w1, b1, w2, b2, w3, b3, out);
}